// round 1
// baseline (speedup 1.0000x reference)
#include <cuda_runtime.h>

#define N_NODES 100000
#define N_EDGES 1600000
#define DIM 64

// scratch (allocation-free: device globals)
__device__ float g_h[(size_t)N_NODES * DIM];   // (1+eps)*x + agg
__device__ float g_t[(size_t)N_NODES * DIM];   // h@W1 + b1
__device__ float g_sum[DIM];
__device__ float g_sq[DIM];
__device__ float g_A[DIM];
__device__ float g_B[DIM];

// ---------------------------------------------------------------------------
// K0: g_h = (1+eps)*x ; zero BN accumulators
// ---------------------------------------------------------------------------
__global__ void init_kernel(const float* __restrict__ x, const float* __restrict__ eps) {
    int i = blockIdx.x * blockDim.x + threadIdx.x;   // one float4 per thread
    float s = 1.0f + *eps;
    float4 v = ((const float4*)x)[i];
    v.x *= s; v.y *= s; v.z *= s; v.w *= s;
    ((float4*)g_h)[i] = v;
    if (blockIdx.x == 0 && threadIdx.x < DIM) {
        g_sum[threadIdx.x] = 0.0f;
        g_sq[threadIdx.x]  = 0.0f;
    }
}

// ---------------------------------------------------------------------------
// K1: edges — msg = relu(x[src] + emb[attr]); red.add into g_h[dst]
// 16 threads per edge, float4 lanes, vectorized global reduction
// ---------------------------------------------------------------------------
__global__ void edge_kernel(const float* __restrict__ x, const float* __restrict__ emb,
                            const int* __restrict__ ei, const int* __restrict__ ea) {
    __shared__ float s_emb[4 * DIM];
    s_emb[threadIdx.x] = emb[threadIdx.x];  // 256 threads == 256 floats
    __syncthreads();

    unsigned gt   = blockIdx.x * 256u + threadIdx.x;
    unsigned e    = gt >> 4;
    unsigned lane = gt & 15u;
    if (e >= N_EDGES) return;

    int src = __ldg(ei + e);
    int dst = __ldg(ei + N_EDGES + e);
    int at  = __ldg(ea + e);

    float4 v  = *(const float4*)(x + (size_t)src * DIM + lane * 4);
    float4 em = *(const float4*)(s_emb + at * DIM + lane * 4);
    float a = fmaxf(v.x + em.x, 0.0f);
    float b = fmaxf(v.y + em.y, 0.0f);
    float c = fmaxf(v.z + em.z, 0.0f);
    float d = fmaxf(v.w + em.w, 0.0f);

    float* p = g_h + (size_t)dst * DIM + lane * 4;
    unsigned long long gp = (unsigned long long)__cvta_generic_to_global(p);
    asm volatile("red.global.add.v4.f32 [%0], {%1,%2,%3,%4};"
                 :: "l"(gp), "f"(a), "f"(b), "f"(c), "f"(d) : "memory");
}

// ---------------------------------------------------------------------------
// K2/K4: 128-row x 64-col tile GEMM, 8x8 register blocking per thread.
// MODE 0: t = g_h @ W1 + b1, write g_t, accumulate column sum/sumsq
// MODE 1: out = relu(g_t*A + B) @ W2 + b2   (normalize fused into smem load)
// ---------------------------------------------------------------------------
#define TILE_R    128
#define IN_STRIDE 132
#define SMEM_FLOATS (DIM * DIM + DIM * IN_STRIDE)   // 4096 + 8448 = 12544

template <int MODE>
__global__ void gemm_kernel(const float* __restrict__ W, const float* __restrict__ bias,
                            float* __restrict__ out_ext) {
    extern __shared__ float sm[];
    float* sW  = sm;                 // [64][64]
    float* sIn = sm + DIM * DIM;     // [64][IN_STRIDE] k-major (transposed tile)

    const float* in  = (MODE == 0) ? g_h : g_t;
    float*       out = (MODE == 0) ? g_t : out_ext;

    int t  = threadIdx.x;            // 128 threads
    int r0 = blockIdx.x * TILE_R;

    // load W (64x64)
    #pragma unroll
    for (int i = 0; i < 8; i++)
        ((float4*)sW)[t + i * 128] = ((const float4*)W)[t + i * 128];

    int kcol = t & 63;
    float ak = 1.0f, bk = 0.0f;
    if (MODE == 1) { ak = g_A[kcol]; bk = g_B[kcol]; }

    // load input tile transposed: sIn[k][row_local]
    int half = t >> 6;  // 0..1
    #pragma unroll 4
    for (int i = 0; i < 64; i++) {
        int rl  = i * 2 + half;
        int row = r0 + rl;
        float v = 0.0f;
        if (row < N_NODES) v = in[(size_t)row * DIM + kcol];
        if (MODE == 1)     v = fmaxf(fmaf(v, ak, bk), 0.0f);
        sIn[kcol * IN_STRIDE + rl] = v;
    }
    __syncthreads();

    int rg = t >> 3;  // 0..15 (row group of 8)
    int cg = t & 7;   // 0..7  (col group of 8)

    float acc[8][8];
    #pragma unroll
    for (int i = 0; i < 8; i++)
        #pragma unroll
        for (int j = 0; j < 8; j++) acc[i][j] = 0.0f;

    #pragma unroll 4
    for (int k = 0; k < 64; k++) {
        float4 a0 = *(const float4*)(sIn + k * IN_STRIDE + rg * 8);
        float4 a1 = *(const float4*)(sIn + k * IN_STRIDE + rg * 8 + 4);
        float4 w0 = *(const float4*)(sW  + k * DIM + cg * 8);
        float4 w1 = *(const float4*)(sW  + k * DIM + cg * 8 + 4);
        float av[8] = {a0.x, a0.y, a0.z, a0.w, a1.x, a1.y, a1.z, a1.w};
        float wv[8] = {w0.x, w0.y, w0.z, w0.w, w1.x, w1.y, w1.z, w1.w};
        #pragma unroll
        for (int i = 0; i < 8; i++)
            #pragma unroll
            for (int j = 0; j < 8; j++)
                acc[i][j] = fmaf(av[i], wv[j], acc[i][j]);
    }

    float bs[8];
    #pragma unroll
    for (int j = 0; j < 8; j++) bs[j] = bias[cg * 8 + j];

    float csum[8], csq[8];
    #pragma unroll
    for (int j = 0; j < 8; j++) { csum[j] = 0.0f; csq[j] = 0.0f; }

    #pragma unroll
    for (int i = 0; i < 8; i++) {
        int row = r0 + rg * 8 + i;
        if (row < N_NODES) {
            float v[8];
            #pragma unroll
            for (int j = 0; j < 8; j++) v[j] = acc[i][j] + bs[j];
            if (MODE == 0) {
                #pragma unroll
                for (int j = 0; j < 8; j++) { csum[j] += v[j]; csq[j] += v[j] * v[j]; }
            }
            float4 o0 = make_float4(v[0], v[1], v[2], v[3]);
            float4 o1 = make_float4(v[4], v[5], v[6], v[7]);
            *(float4*)(out + (size_t)row * DIM + cg * 8)     = o0;
            *(float4*)(out + (size_t)row * DIM + cg * 8 + 4) = o1;
        }
    }

    if (MODE == 0) {
        __syncthreads();          // done reading sIn; reuse as reduction scratch
        float* red = sIn;         // needs 2048 floats
        #pragma unroll
        for (int j = 0; j < 8; j++) {
            red[rg * 64 + cg * 8 + j]        = csum[j];
            red[(16 + rg) * 64 + cg * 8 + j] = csq[j];
        }
        __syncthreads();
        if (t < 64) {
            float s = 0.0f;
            #pragma unroll
            for (int g = 0; g < 16; g++) s += red[g * 64 + t];
            atomicAdd(&g_sum[t], s);
        } else {
            int c = t - 64;
            float s = 0.0f;
            #pragma unroll
            for (int g = 0; g < 16; g++) s += red[(16 + g) * 64 + c];
            atomicAdd(&g_sq[c], s);
        }
    }
}

// ---------------------------------------------------------------------------
// K3: fold BN stats into per-column affine  y = t*A + B
// ---------------------------------------------------------------------------
__global__ void bn_kernel(const float* __restrict__ gamma, const float* __restrict__ beta) {
    int c = threadIdx.x;
    const float inv = 1.0f / (float)N_NODES;
    float mu  = g_sum[c] * inv;
    float var = g_sq[c] * inv - mu * mu;
    float a   = gamma[c] * rsqrtf(var + 1e-5f);
    g_A[c] = a;
    g_B[c] = fmaf(-mu, a, beta[c]);
}

// ---------------------------------------------------------------------------
extern "C" void kernel_launch(void* const* d_in, const int* in_sizes, int n_in,
                              void* d_out, int out_size) {
    const float* x     = (const float*)d_in[0];
    const float* emb   = (const float*)d_in[1];
    const float* eps   = (const float*)d_in[2];
    const float* W1    = (const float*)d_in[3];
    const float* b1    = (const float*)d_in[4];
    const float* gamma = (const float*)d_in[5];
    const float* beta  = (const float*)d_in[6];
    const float* W2    = (const float*)d_in[7];
    const float* b2    = (const float*)d_in[8];
    const int*   ei    = (const int*)d_in[9];
    const int*   ea    = (const int*)d_in[10];
    float*       out   = (float*)d_out;

    const int smem_bytes = SMEM_FLOATS * 4;  // 50176 > 48K: opt in
    cudaFuncSetAttribute(gemm_kernel<0>, cudaFuncAttributeMaxDynamicSharedMemorySize, smem_bytes);
    cudaFuncSetAttribute(gemm_kernel<1>, cudaFuncAttributeMaxDynamicSharedMemorySize, smem_bytes);

    init_kernel<<<(N_NODES * DIM) / (256 * 4), 256>>>(x, eps);          // 6250 blocks
    edge_kernel<<<(N_EDGES * 16 + 255) / 256, 256>>>(x, emb, ei, ea);   // 100000 blocks
    const int gblocks = (N_NODES + TILE_R - 1) / TILE_R;                // 782
    gemm_kernel<0><<<gblocks, 128, smem_bytes>>>(W1, b1, nullptr);
    bn_kernel<<<1, DIM>>>(gamma, beta);
    gemm_kernel<1><<<gblocks, 128, smem_bytes>>>(W2, b2, out);
}

// round 2
// speedup vs baseline: 1.1011x; 1.1011x over previous
#include <cuda_runtime.h>

#define N_NODES 100000
#define N_EDGES 1600000
#define DIM 64
#define SCAN_CHUNK 1024
#define NCH ((N_NODES + SCAN_CHUNK - 1) / SCAN_CHUNK)   // 98

// scratch (allocation-free: device globals)
__device__ float g_h[(size_t)N_NODES * DIM];   // (1+eps)*x + agg
__device__ float g_t[(size_t)N_NODES * DIM];   // h@W1 + b1
__device__ float g_sum[DIM];
__device__ float g_sq[DIM];
__device__ int   g_deg[N_NODES];
__device__ int   g_off[N_NODES];
__device__ int   g_cur[N_NODES];
__device__ int   g_csum[NCH];
__device__ int   g_cbase[NCH];
__device__ unsigned g_es[N_EDGES];             // (attr<<28) | src

// ---------------------------------------------------------------------------
// K0: zero degree counters + BN accumulators
// ---------------------------------------------------------------------------
__global__ void zero_kernel() {
    int i = blockIdx.x * 256 + threadIdx.x;
    if (i < N_NODES) g_deg[i] = 0;
    if (i < DIM) { g_sum[i] = 0.0f; g_sq[i] = 0.0f; }
}

// ---------------------------------------------------------------------------
// K1: histogram of dst
// ---------------------------------------------------------------------------
__global__ void hist_kernel(const int* __restrict__ ei) {
    int e = blockIdx.x * 256 + threadIdx.x;
    if (e < N_EDGES) atomicAdd(&g_deg[ei[N_EDGES + e]], 1);
}

// ---------------------------------------------------------------------------
// K2a/b/c: exclusive prefix sum of g_deg -> g_off (and g_cur copy)
// ---------------------------------------------------------------------------
__global__ void scanA_kernel() {             // 98 blocks x 256
    __shared__ int sm[256];
    int base = blockIdx.x * SCAN_CHUNK;
    int s = 0;
    for (int i = threadIdx.x; i < SCAN_CHUNK; i += 256) {
        int idx = base + i;
        if (idx < N_NODES) s += g_deg[idx];
    }
    sm[threadIdx.x] = s; __syncthreads();
    for (int st = 128; st > 0; st >>= 1) {
        if (threadIdx.x < st) sm[threadIdx.x] += sm[threadIdx.x + st];
        __syncthreads();
    }
    if (threadIdx.x == 0) g_csum[blockIdx.x] = sm[0];
}

__global__ void scanB_kernel() {             // 1 x 32
    if (threadIdx.x == 0) {
        int run = 0;
        for (int i = 0; i < NCH; i++) { g_cbase[i] = run; run += g_csum[i]; }
    }
}

__global__ void scanC_kernel() {             // 98 blocks x 1024
    __shared__ int sm[SCAN_CHUNK];
    int idx = blockIdx.x * SCAN_CHUNK + threadIdx.x;
    int d = (idx < N_NODES) ? g_deg[idx] : 0;
    sm[threadIdx.x] = d; __syncthreads();
    for (int st = 1; st < SCAN_CHUNK; st <<= 1) {
        int t = 0;
        if ((int)threadIdx.x >= st) t = sm[threadIdx.x - st];
        __syncthreads();
        sm[threadIdx.x] += t;
        __syncthreads();
    }
    int ex = sm[threadIdx.x] - d + g_cbase[blockIdx.x];
    if (idx < N_NODES) { g_off[idx] = ex; g_cur[idx] = ex; }
}

// ---------------------------------------------------------------------------
// K3: scatter packed (attr,src) into CSR slots
// ---------------------------------------------------------------------------
__global__ void scatter_kernel(const int* __restrict__ ei, const int* __restrict__ ea) {
    int e = blockIdx.x * 256 + threadIdx.x;
    if (e >= N_EDGES) return;
    int src = ei[e];
    int dst = ei[N_EDGES + e];
    unsigned at = (unsigned)ea[e];
    int pos = atomicAdd(&g_cur[dst], 1);
    g_es[pos] = (unsigned)src | (at << 28);
}

// ---------------------------------------------------------------------------
// K4: aggregate — per node, register-accumulate relu(x[src]+emb[attr]),
//     write h = (1+eps)*x + agg once. 16 lanes per node (float4 each).
// ---------------------------------------------------------------------------
__global__ void agg_kernel(const float* __restrict__ x, const float* __restrict__ emb,
                           const float* __restrict__ eps) {
    __shared__ float s_emb[4 * DIM];
    s_emb[threadIdx.x] = emb[threadIdx.x];   // 256 threads == 256 floats
    __syncthreads();

    unsigned gt = blockIdx.x * 256u + threadIdx.x;
    unsigned n = gt >> 4;
    unsigned lane = gt & 15u;
    if (n >= N_NODES) return;

    int off = g_off[n];
    int deg = g_deg[n];
    float s = 1.0f + __ldg(eps);

    float4 acc = *(const float4*)(x + (size_t)n * DIM + lane * 4);
    acc.x *= s; acc.y *= s; acc.z *= s; acc.w *= s;

    int j = 0;
    for (; j + 2 <= deg; j += 2) {
        unsigned p0 = g_es[off + j];
        unsigned p1 = g_es[off + j + 1];
        unsigned s0 = p0 & 0x0FFFFFFFu, a0 = p0 >> 28;
        unsigned s1 = p1 & 0x0FFFFFFFu, a1 = p1 >> 28;
        float4 v0 = *(const float4*)(x + (size_t)s0 * DIM + lane * 4);
        float4 v1 = *(const float4*)(x + (size_t)s1 * DIM + lane * 4);
        float4 e0 = *(const float4*)(s_emb + a0 * DIM + lane * 4);
        float4 e1 = *(const float4*)(s_emb + a1 * DIM + lane * 4);
        acc.x += fmaxf(v0.x + e0.x, 0.0f) + fmaxf(v1.x + e1.x, 0.0f);
        acc.y += fmaxf(v0.y + e0.y, 0.0f) + fmaxf(v1.y + e1.y, 0.0f);
        acc.z += fmaxf(v0.z + e0.z, 0.0f) + fmaxf(v1.z + e1.z, 0.0f);
        acc.w += fmaxf(v0.w + e0.w, 0.0f) + fmaxf(v1.w + e1.w, 0.0f);
    }
    if (j < deg) {
        unsigned p0 = g_es[off + j];
        unsigned s0 = p0 & 0x0FFFFFFFu, a0 = p0 >> 28;
        float4 v0 = *(const float4*)(x + (size_t)s0 * DIM + lane * 4);
        float4 e0 = *(const float4*)(s_emb + a0 * DIM + lane * 4);
        acc.x += fmaxf(v0.x + e0.x, 0.0f);
        acc.y += fmaxf(v0.y + e0.y, 0.0f);
        acc.z += fmaxf(v0.z + e0.z, 0.0f);
        acc.w += fmaxf(v0.w + e0.w, 0.0f);
    }
    *(float4*)(g_h + (size_t)n * DIM + lane * 4) = acc;
}

// ---------------------------------------------------------------------------
// K5/K6: 128-row x 64-col tile GEMM, 8x8 register blocking per thread.
// MODE 0: t = g_h @ W1 + b1, write g_t, accumulate column sum/sumsq
// MODE 1: out = relu(t*A + B) @ W2 + b2, BN affine computed from g_sum/g_sq
// ---------------------------------------------------------------------------
#define TILE_R    128
#define IN_STRIDE 132
#define SMEM_FLOATS (DIM * DIM + DIM * IN_STRIDE)   // 12544

template <int MODE>
__global__ void gemm_kernel(const float* __restrict__ W, const float* __restrict__ bias,
                            const float* __restrict__ gamma, const float* __restrict__ beta,
                            float* __restrict__ out_ext) {
    extern __shared__ float sm[];
    float* sW  = sm;                 // [64][64]
    float* sIn = sm + DIM * DIM;     // [64][IN_STRIDE] k-major (transposed tile)

    const float* in  = (MODE == 0) ? g_h : g_t;
    float*       out = (MODE == 0) ? g_t : out_ext;

    int t  = threadIdx.x;            // 128 threads
    int r0 = blockIdx.x * TILE_R;

    #pragma unroll
    for (int i = 0; i < 8; i++)
        ((float4*)sW)[t + i * 128] = ((const float4*)W)[t + i * 128];

    int kcol = t & 63;
    float ak = 1.0f, bk = 0.0f;
    if (MODE == 1) {
        const float inv = 1.0f / (float)N_NODES;
        float mu  = g_sum[kcol] * inv;
        float var = g_sq[kcol] * inv - mu * mu;
        float a   = gamma[kcol] * rsqrtf(var + 1e-5f);
        ak = a;
        bk = fmaf(-mu, a, beta[kcol]);
    }

    int half = t >> 6;  // 0..1
    #pragma unroll 4
    for (int i = 0; i < 64; i++) {
        int rl  = i * 2 + half;
        int row = r0 + rl;
        float v = 0.0f;
        if (row < N_NODES) v = in[(size_t)row * DIM + kcol];
        if (MODE == 1)     v = fmaxf(fmaf(v, ak, bk), 0.0f);
        sIn[kcol * IN_STRIDE + rl] = v;
    }
    __syncthreads();

    int rg = t >> 3;  // 0..15
    int cg = t & 7;   // 0..7

    float acc[8][8];
    #pragma unroll
    for (int i = 0; i < 8; i++)
        #pragma unroll
        for (int j = 0; j < 8; j++) acc[i][j] = 0.0f;

    #pragma unroll 4
    for (int k = 0; k < 64; k++) {
        float4 a0 = *(const float4*)(sIn + k * IN_STRIDE + rg * 8);
        float4 a1 = *(const float4*)(sIn + k * IN_STRIDE + rg * 8 + 4);
        float4 w0 = *(const float4*)(sW  + k * DIM + cg * 8);
        float4 w1 = *(const float4*)(sW  + k * DIM + cg * 8 + 4);
        float av[8] = {a0.x, a0.y, a0.z, a0.w, a1.x, a1.y, a1.z, a1.w};
        float wv[8] = {w0.x, w0.y, w0.z, w0.w, w1.x, w1.y, w1.z, w1.w};
        #pragma unroll
        for (int i = 0; i < 8; i++)
            #pragma unroll
            for (int j = 0; j < 8; j++)
                acc[i][j] = fmaf(av[i], wv[j], acc[i][j]);
    }

    float bs[8];
    #pragma unroll
    for (int j = 0; j < 8; j++) bs[j] = bias[cg * 8 + j];

    float csum[8], csq[8];
    #pragma unroll
    for (int j = 0; j < 8; j++) { csum[j] = 0.0f; csq[j] = 0.0f; }

    #pragma unroll
    for (int i = 0; i < 8; i++) {
        int row = r0 + rg * 8 + i;
        if (row < N_NODES) {
            float v[8];
            #pragma unroll
            for (int j = 0; j < 8; j++) v[j] = acc[i][j] + bs[j];
            if (MODE == 0) {
                #pragma unroll
                for (int j = 0; j < 8; j++) { csum[j] += v[j]; csq[j] += v[j] * v[j]; }
            }
            float4 o0 = make_float4(v[0], v[1], v[2], v[3]);
            float4 o1 = make_float4(v[4], v[5], v[6], v[7]);
            *(float4*)(out + (size_t)row * DIM + cg * 8)     = o0;
            *(float4*)(out + (size_t)row * DIM + cg * 8 + 4) = o1;
        }
    }

    if (MODE == 0) {
        __syncthreads();
        float* red = sIn;
        #pragma unroll
        for (int j = 0; j < 8; j++) {
            red[rg * 64 + cg * 8 + j]        = csum[j];
            red[(16 + rg) * 64 + cg * 8 + j] = csq[j];
        }
        __syncthreads();
        if (t < 64) {
            float s = 0.0f;
            #pragma unroll
            for (int g = 0; g < 16; g++) s += red[g * 64 + t];
            atomicAdd(&g_sum[t], s);
        } else {
            int c = t - 64;
            float s = 0.0f;
            #pragma unroll
            for (int g = 0; g < 16; g++) s += red[(16 + g) * 64 + c];
            atomicAdd(&g_sq[c], s);
        }
    }
}

// ---------------------------------------------------------------------------
extern "C" void kernel_launch(void* const* d_in, const int* in_sizes, int n_in,
                              void* d_out, int out_size) {
    const float* x     = (const float*)d_in[0];
    const float* emb   = (const float*)d_in[1];
    const float* eps   = (const float*)d_in[2];
    const float* W1    = (const float*)d_in[3];
    const float* b1    = (const float*)d_in[4];
    const float* gamma = (const float*)d_in[5];
    const float* beta  = (const float*)d_in[6];
    const float* W2    = (const float*)d_in[7];
    const float* b2    = (const float*)d_in[8];
    const int*   ei    = (const int*)d_in[9];
    const int*   ea    = (const int*)d_in[10];
    float*       out   = (float*)d_out;

    const int smem_bytes = SMEM_FLOATS * 4;  // 50176 > 48K: opt in
    cudaFuncSetAttribute(gemm_kernel<0>, cudaFuncAttributeMaxDynamicSharedMemorySize, smem_bytes);
    cudaFuncSetAttribute(gemm_kernel<1>, cudaFuncAttributeMaxDynamicSharedMemorySize, smem_bytes);

    const int eblocks = (N_EDGES + 255) / 256;            // 6250
    zero_kernel<<<(N_NODES + 255) / 256, 256>>>();
    hist_kernel<<<eblocks, 256>>>(ei);
    scanA_kernel<<<NCH, 256>>>();
    scanB_kernel<<<1, 32>>>();
    scanC_kernel<<<NCH, SCAN_CHUNK>>>();
    scatter_kernel<<<eblocks, 256>>>(ei, ea);
    agg_kernel<<<(N_NODES * 16 + 255) / 256, 256>>>(x, emb, eps);
    const int gblocks = (N_NODES + TILE_R - 1) / TILE_R;  // 782
    gemm_kernel<0><<<gblocks, 128, smem_bytes>>>(W1, b1, nullptr, nullptr, nullptr);
    gemm_kernel<1><<<gblocks, 128, smem_bytes>>>(W2, b2, gamma, beta, out);
}